// round 15
// baseline (speedup 1.0000x reference)
#include <cuda_runtime.h>
#include <cuda_bf16.h>
#include <cuda_fp16.h>
#include <stdint.h>
#include <math.h>

#define L 96
#define LL2 (L*L)
#define L3 (L*L*L)
#define ZP 98                 // z halo: zp=0 <-> z=95, zp=1..96 <-> z=0..95, zp=97 <-> z=0
#define NPAIR 90              // y1 pair slots per row: P[s] = {w(s), w(s+8)}, s=0..89 (zp coords)

typedef unsigned long long ull;

// ---------------- device scratch (allocation-free rule) ----------------
// bonds: per site 4 uint4 (t=0..3): {x=bf16hi pair ch(2t,2t+1), y=bf16lo pair,
//                                    z=bf16hi pair ch(2t+8,2t+9), w=bf16lo pair}
__device__ __align__(16) uint4 g_bp[L * L * ZP * 4];
// y1 pair-mirrored: per row, per pair s (0..89), per word t: uint4 =
//   {w(s).lo32, w(s).hi32, w(s+8).lo32, w(s+8).hi32}; w = fp16 y1 word (see R13).
__device__ __align__(16) uint4 g_y1q[L * L * NPAIR * 4];
// B fragments: conv1 uint4 {bh0,bh1,bl0,bl1};
//              conv2 uint4 {nt0.b0, nt0.b1, nt1.b0, nt1.b1} (two n-tiles per frag)
__device__ __align__(16) uint4 g_Bf1[27 * 2 * 32];   // conv1, bf16 hi+lo
__device__ __align__(16) uint4 g_Bf2[27 * 2 * 32];   // conv2, fp16 single, nt-paired
__device__ float g_part[864 * 32];

// ---------------- helpers ----------------
__device__ __forceinline__ int wrapi(int a) {
    return a < 0 ? a + L : (a >= L ? a - L : a);
}
__device__ __forceinline__ float eluf(float x) {
    return x > 0.f ? x : (__expf(x) - 1.f);
}
__device__ __forceinline__ void split2bf(float v0, float v1, uint32_t& hi, uint32_t& lo) {
    __nv_bfloat16 h0 = __float2bfloat16(v0);
    __nv_bfloat16 h1 = __float2bfloat16(v1);
    __nv_bfloat16 l0 = __float2bfloat16(v0 - __bfloat162float(h0));
    __nv_bfloat16 l1 = __float2bfloat16(v1 - __bfloat162float(h1));
    hi = (uint32_t)__bfloat16_as_ushort(h0) | ((uint32_t)__bfloat16_as_ushort(h1) << 16);
    lo = (uint32_t)__bfloat16_as_ushort(l0) | ((uint32_t)__bfloat16_as_ushort(l1) << 16);
}
__device__ __forceinline__ uint32_t h2pack(float a, float b) {
    __half2 h = __floats2half2_rn(a, b);
    return *(uint32_t*)&h;
}
// write y1 word t of site z (plus halo aliases) into the pair-mirrored layout
__device__ __forceinline__ void store_y1(ull* rowbase, int z, int t, ull v) {
    int zp = z + 1;
    if (zp <= 89) rowbase[(zp * 4 + t) * 2] = v;              // pair zp, lo member
    if (zp >= 8)  rowbase[((zp - 8) * 4 + t) * 2 + 1] = v;    // pair zp-8, hi member
    if (z == 0)   rowbase[(89 * 4 + t) * 2 + 1] = v;          // zp alias 97 -> pair 89 hi
    if (z == L-1) rowbase[t * 2] = v;                         // zp alias 0  -> pair 0 lo
}

#define MMA_BF16(D, A0, A1, A2, A3, B0, B1)                                 \
    asm("mma.sync.aligned.m16n8k16.row.col.f32.bf16.bf16.f32 "              \
        "{%0,%1,%2,%3}, {%4,%5,%6,%7}, {%8,%9}, {%0,%1,%2,%3};"             \
        : "+f"((D)[0]), "+f"((D)[1]), "+f"((D)[2]), "+f"((D)[3])            \
        : "r"(A0), "r"(A1), "r"(A2), "r"(A3), "r"(B0), "r"(B1))

#define MMA_F16(D, A0, A1, A2, A3, B0, B1)                                  \
    asm("mma.sync.aligned.m16n8k16.row.col.f32.f16.f16.f32 "                \
        "{%0,%1,%2,%3}, {%4,%5,%6,%7}, {%8,%9}, {%0,%1,%2,%3};"             \
        : "+f"((D)[0]), "+f"((D)[1]), "+f"((D)[2]), "+f"((D)[3])            \
        : "r"(A0), "r"(A1), "r"(A2), "r"(A3), "r"(B0), "r"(B1))

// ---------------- Kernel 1: bonds -> bf16 hi/lo uint4, z-halo ----------------
__global__ __launch_bounds__(256) void bonds_kernel(const int* __restrict__ lx,
                                                    const float* __restrict__ tet) {
    int idx = blockIdx.x * 256 + threadIdx.x;
    if (idx >= L3) return;
    int z = idx % L;
    int y = (idx / L) % L;
    int x = idx / LL2;

    float t00 = tet[0], t01 = tet[1], t10 = tet[2], t11 = tet[3];
    float d00 = t00 * t00 + t01 * t01;
    float d01 = t00 * t10 + t01 * t11;
    float d11 = t10 * t10 + t11 * t11;
    float dt[4] = {d00, d01, d01, d11};

    int4 a = *(const int4*)&lx[idx * 4];
    int a0 = a.x, a1 = a.y, a2 = a.z, a3 = a.w;
    int xm = x ? x - 1 : L - 1;
    int ym = y ? y - 1 : L - 1;
    int zm = z ? z - 1 : L - 1;
    int b1 = lx[((xm * L + y) * L + z) * 4 + 1];
    int b2 = lx[((x * L + ym) * L + z) * 4 + 2];
    int b3 = lx[((x * L + y) * L + zm) * 4 + 3];

    float v[16];
    v[0] = dt[a0 * 2 + a1];  v[1] = dt[a0 * 2 + a2];  v[2]  = dt[a0 * 2 + a3];
    v[3] = dt[a0 * 2 + b1];  v[4] = dt[a0 * 2 + b2];  v[5]  = dt[a0 * 2 + b3];
    v[6] = dt[a1 * 2 + a2];  v[7] = dt[a2 * 2 + a3];  v[8]  = dt[a3 * 2 + a1];
    v[9] = dt[b1 * 2 + b2];  v[10] = dt[b2 * 2 + b3]; v[11] = dt[b3 * 2 + b1];
    v[12] = v[13] = v[14] = v[15] = 0.f;

    uint4 q[4];
#pragma unroll
    for (int t = 0; t < 4; t++) {
        split2bf(v[2 * t], v[2 * t + 1], q[t].x, q[t].y);
        split2bf(v[2 * t + 8], v[2 * t + 9], q[t].z, q[t].w);
    }

    size_t rb = (size_t)(x * L + y) * (ZP * 4);
    uint4* dst = &g_bp[rb + (size_t)(z + 1) * 4];
#pragma unroll
    for (int t = 0; t < 4; t++) dst[t] = q[t];
    if (z == 0) {
        uint4* d2 = &g_bp[rb + 97 * 4];
#pragma unroll
        for (int t = 0; t < 4; t++) d2[t] = q[t];
    }
    if (z == L - 1) {
        uint4* d2 = &g_bp[rb];
#pragma unroll
        for (int t = 0; t < 4; t++) d2[t] = q[t];
    }
}

// ---------------- Kernel 2: weight -> B-fragment prep ----------------
__global__ __launch_bounds__(256) void prep_kernel(const float* __restrict__ w1,
                                                   const float* __restrict__ w2) {
    int i = blockIdx.x * 256 + threadIdx.x;
    if (i < 27 * 2 * 32) {  // conv1: bf16 hi+lo
        int lane = i & 31, nt = (i >> 5) & 1, tap = i >> 6;
        int t = lane & 3;
        int n = nt * 8 + (lane >> 2);
        int k0 = t * 2;
        float v00 = (k0 < 12)      ? w1[(tap * 12 + k0) * 16 + n]      : 0.f;
        float v01 = (k0 + 1 < 12)  ? w1[(tap * 12 + k0 + 1) * 16 + n]  : 0.f;
        float v10 = (k0 + 8 < 12)  ? w1[(tap * 12 + k0 + 8) * 16 + n]  : 0.f;
        float v11 = (k0 + 9 < 12)  ? w1[(tap * 12 + k0 + 9) * 16 + n]  : 0.f;
        uint4 o;
        split2bf(v00, v01, o.x, o.z);
        split2bf(v10, v11, o.y, o.w);
        g_Bf1[i] = o;
    }
    int j = i - 27 * 2 * 32;
    if (j >= 0 && j < 27 * 2 * 32) {  // conv2: fp16 single, two n-tiles per uint4
        int lane = j & 31, ntp = (j >> 5) & 1, tap = j >> 6;
        int t = lane & 3;
        int k0 = t * 2;
        int n0 = (ntp * 2) * 8 + (lane >> 2);
        int n1 = n0 + 8;
        uint4 o;
        o.x = h2pack(w2[(tap * 16 + k0) * 32 + n0],
                     w2[(tap * 16 + k0 + 1) * 32 + n0]);
        o.y = h2pack(w2[(tap * 16 + k0 + 8) * 32 + n0],
                     w2[(tap * 16 + k0 + 9) * 32 + n0]);
        o.z = h2pack(w2[(tap * 16 + k0) * 32 + n1],
                     w2[(tap * 16 + k0 + 1) * 32 + n1]);
        o.w = h2pack(w2[(tap * 16 + k0 + 8) * 32 + n1],
                     w2[(tap * 16 + k0 + 9) * 32 + n1]);
        g_Bf2[j] = o;
    }
}

// ---------------- conv1: bf16 3-term, 1728 CTAs, pair-mirrored y1 stores ----------------
// Warp tile = 32 z-consecutive sites. 8 warps/CTA, 2 tiles/warp.
__global__ __launch_bounds__(256, 2) void conv1_kernel(const float* __restrict__ bias) {
    extern __shared__ uint4 sB4[];
    const int tid = threadIdx.x;
    const int wid = tid >> 5, lane = tid & 31;
    const int t = lane & 3, r = lane >> 2;

    for (int i = tid; i < 27 * 2 * 32; i += 256) sB4[i] = __ldg(g_Bf1 + i);
    __syncthreads();

    const int wg = blockIdx.x * 8 + wid;

    for (int it = 0; it < 2; it++) {
        int tile = wg * 2 + it;
        int tz = tile % 3;
        int ty = (tile / 3) % L;
        int tx = tile / (3 * L);
        int z0 = tz * 32;
        const int laneoff = (z0 + r) * 4 + t;

        int xs[3], ys[3];
#pragma unroll
        for (int k = 0; k < 3; k++) { xs[k] = wrapi(tx + k - 1); ys[k] = wrapi(ty + k - 1); }

        float d[2][2][4];
#pragma unroll
        for (int nt = 0; nt < 2; nt++) {
            float b0 = __ldg(bias + nt * 8 + t * 2);
            float b1 = __ldg(bias + nt * 8 + t * 2 + 1);
            d[0][nt][0] = b0; d[0][nt][1] = b1; d[0][nt][2] = b0; d[0][nt][3] = b1;
            d[1][nt][0] = b0; d[1][nt][1] = b1; d[1][nt][2] = b0; d[1][nt][3] = b1;
        }

#pragma unroll
        for (int kd = 0; kd < 3; kd++) {
#pragma unroll
            for (int kh = 0; kh < 3; kh++) {
                const uint4* rp = g_bp + (size_t)((xs[kd] * L + ys[kh]) * (ZP * 4) + laneoff);
                uint4 q[3][4];
#pragma unroll
                for (int kw = 0; kw < 3; kw++)
#pragma unroll
                    for (int jj = 0; jj < 4; jj++)
                        q[kw][jj] = __ldg(rp + kw * 4 + jj * 32);
#pragma unroll
                for (int kw = 0; kw < 3; kw++) {
                    const int tap = (kd * 3 + kh) * 3 + kw;
#pragma unroll
                    for (int nt = 0; nt < 2; nt++) {
                        uint4 wb = sB4[(tap * 2 + nt) * 32 + lane];  // 1 LDS.128
#pragma unroll
                        for (int mt = 0; mt < 2; mt++) {
                            const uint4& za = q[kw][mt * 2];
                            const uint4& zb = q[kw][mt * 2 + 1];
                            MMA_BF16(d[mt][nt], za.x, zb.x, za.z, zb.z, wb.x, wb.y);
                            MMA_BF16(d[mt][nt], za.x, zb.x, za.z, zb.z, wb.z, wb.w);
                            MMA_BF16(d[mt][nt], za.y, zb.y, za.w, zb.w, wb.x, wb.y);
                        }
                    }
                }
            }
        }

        // ELU -> fp16 word, mirrored into pair layout (word t = {nt0 pair | nt1 pair})
        ull* rowbase = (ull*)g_y1q + (size_t)(tx * L + ty) * (NPAIR * 8);
#pragma unroll
        for (int mt = 0; mt < 2; mt++) {
            int za = z0 + mt * 16 + r;
            int zb = za + 8;
            ull va = (ull)h2pack(eluf(d[mt][0][0]), eluf(d[mt][0][1])) |
                     ((ull)h2pack(eluf(d[mt][1][0]), eluf(d[mt][1][1])) << 32);
            ull vb = (ull)h2pack(eluf(d[mt][0][2]), eluf(d[mt][0][3])) |
                     ((ull)h2pack(eluf(d[mt][1][2]), eluf(d[mt][1][3])) << 32);
            store_y1(rowbase, za, t, va);
            store_y1(rowbase, zb, t, vb);
        }
    }
}

// ---------------- conv2: fp16 single-term, paired A (54 LDG.128) + paired B ----------------
__global__ __launch_bounds__(256, 3) void conv2_kernel(const float* __restrict__ bias) {
    extern __shared__ uint4 sB4c[];
    __shared__ float red[8][32];

    const int tid = threadIdx.x;
    const int wid = tid >> 5, lane = tid & 31;
    const int t = lane & 3, r = lane >> 2;

    for (int i = tid; i < 27 * 2 * 32; i += 256) sB4c[i] = __ldg(g_Bf2 + i);
    __syncthreads();

    const int wg = blockIdx.x * 8 + wid;

    float psum0[4], psum1[4];
#pragma unroll
    for (int nt = 0; nt < 4; nt++) { psum0[nt] = 0.f; psum1[nt] = 0.f; }

    for (int it = 0; it < 4; it++) {
        int tile = wg * 4 + it;
        int tz = tile % 3;
        int ty = (tile / 3) % L;
        int tx = tile / (3 * L);
        int z0 = tz * 32;

        int xs[3], ys[3];
#pragma unroll
        for (int k = 0; k < 3; k++) { xs[k] = wrapi(tx + k - 1); ys[k] = wrapi(ty + k - 1); }

        float d[2][4][4];
#pragma unroll
        for (int nt = 0; nt < 4; nt++) {
            float b0 = __ldg(bias + nt * 8 + t * 2);
            float b1 = __ldg(bias + nt * 8 + t * 2 + 1);
            d[0][nt][0] = b0; d[0][nt][1] = b1; d[0][nt][2] = b0; d[0][nt][3] = b1;
            d[1][nt][0] = b0; d[1][nt][1] = b1; d[1][nt][2] = b0; d[1][nt][3] = b1;
        }

#pragma unroll
        for (int kd = 0; kd < 3; kd++) {
#pragma unroll
            for (int kh = 0; kh < 3; kh++) {
                // one base; each (kw,mt) pair fragment = one LDG.128 at [R+imm]
                const uint4* rp = g_y1q +
                    (size_t)(xs[kd] * L + ys[kh]) * (NPAIR * 4) + (size_t)(z0 + r) * 4 + t;
                uint4 q[2][3];
#pragma unroll
                for (int mt = 0; mt < 2; mt++)
#pragma unroll
                    for (int kw = 0; kw < 3; kw++)
                        q[mt][kw] = __ldg(rp + kw * 4 + mt * 64);
#pragma unroll
                for (int kw = 0; kw < 3; kw++) {
                    const int tap = (kd * 3 + kh) * 3 + kw;
#pragma unroll
                    for (int ntp = 0; ntp < 2; ntp++) {
                        uint4 wb = sB4c[(tap * 2 + ntp) * 32 + lane];  // 1 LDS.128 -> 2 nt
#pragma unroll
                        for (int mt = 0; mt < 2; mt++) {
                            const uint4& p = q[mt][kw];
                            // {p.x,p.y}=site s, {p.z,p.w}=site s+8
                            MMA_F16(d[mt][2 * ntp],     p.x, p.z, p.y, p.w, wb.x, wb.y);
                            MMA_F16(d[mt][2 * ntp + 1], p.x, p.z, p.y, p.w, wb.z, wb.w);
                        }
                    }
                }
            }
        }

#pragma unroll
        for (int nt = 0; nt < 4; nt++) {
            psum0[nt] += eluf(d[0][nt][0]) + eluf(d[0][nt][2]) +
                         eluf(d[1][nt][0]) + eluf(d[1][nt][2]);
            psum1[nt] += eluf(d[0][nt][1]) + eluf(d[0][nt][3]) +
                         eluf(d[1][nt][1]) + eluf(d[1][nt][3]);
        }
    }

    // deterministic reduction over row-slots r (lane bits 2..4)
#pragma unroll
    for (int off = 4; off <= 16; off <<= 1)
#pragma unroll
        for (int nt = 0; nt < 4; nt++) {
            psum0[nt] += __shfl_xor_sync(0xffffffffu, psum0[nt], off);
            psum1[nt] += __shfl_xor_sync(0xffffffffu, psum1[nt], off);
        }
    if (r == 0) {
#pragma unroll
        for (int nt = 0; nt < 4; nt++) {
            red[wid][nt * 8 + t * 2] = psum0[nt];
            red[wid][nt * 8 + t * 2 + 1] = psum1[nt];
        }
    }
    __syncthreads();
    if (tid < 32) {
        float s = 0.f;
#pragma unroll
        for (int w = 0; w < 8; w++) s += red[w][tid];
        g_part[blockIdx.x * 32 + tid] = s;
    }
}

// ---------------- final reduction (deterministic, 1024 threads) ----------------
__global__ __launch_bounds__(1024) void final_kernel(const float* __restrict__ wd,
                                                     float* __restrict__ out) {
    __shared__ float sm[1024];
    int tt = threadIdx.x, ch = tt & 31, grp = tt >> 5;  // 32 groups of 32 channels
    float s = 0.f;
    for (int b = grp; b < 864; b += 32) s += g_part[b * 32 + ch];  // 27 indep loads
    sm[tt] = s;
    __syncthreads();
    if (tt < 32) {
        float v = 0.f;
#pragma unroll
        for (int g = 0; g < 32; g++) v += sm[g * 32 + tt];
        v = (v / (float)L3) * __ldg(wd + tt);
#pragma unroll
        for (int off = 16; off; off >>= 1)
            v += __shfl_xor_sync(0xffffffffu, v, off);
        if (tt == 0) out[0] = v;
    }
}

// ---------------- launch ----------------
extern "C" void kernel_launch(void* const* d_in, const int* in_sizes, int n_in,
                              void* d_out, int out_size) {
    (void)in_sizes; (void)n_in; (void)out_size;
    const int*   lx  = (const int*)d_in[0];
    const float* tet = (const float*)d_in[1];
    const float* w1  = (const float*)d_in[2];
    const float* b1  = (const float*)d_in[3];
    const float* w2  = (const float*)d_in[4];
    const float* b2  = (const float*)d_in[5];
    const float* wd  = (const float*)d_in[6];

    const int SMEM1 = 27 * 2 * 32 * 16;  // 27648 B
    const int SMEM2 = 27 * 2 * 32 * 16;  // 27648 B
    cudaFuncSetAttribute(conv1_kernel,
                         cudaFuncAttributeMaxDynamicSharedMemorySize, SMEM1);
    cudaFuncSetAttribute(conv2_kernel,
                         cudaFuncAttributeMaxDynamicSharedMemorySize, SMEM2);

    bonds_kernel<<<3456, 256>>>(lx, tet);
    prep_kernel<<<41, 256>>>(w1, w2);
    conv1_kernel<<<1728, 256, SMEM1>>>(b1);
    conv2_kernel<<<864, 256, SMEM2>>>(b2);
    final_kernel<<<1, 1024>>>(wd, (float*)d_out);
}

// round 16
// speedup vs baseline: 1.0706x; 1.0706x over previous
#include <cuda_runtime.h>
#include <cuda_bf16.h>
#include <cuda_fp16.h>
#include <stdint.h>
#include <math.h>

#define L 96
#define LL2 (L*L)
#define L3 (L*L*L)
#define ZP 98                 // z halo: zp=0 <-> z=95, zp=1..96 <-> z=0..95, zp=97 <-> z=0

typedef unsigned long long ull;

// ---------------- device scratch (allocation-free rule) ----------------
// bonds: per site 4 uint4 (t=0..3): {x=bf16hi pair ch(2t,2t+1), y=bf16lo pair,
//                                    z=bf16hi pair ch(2t+8,2t+9), w=bf16lo pair}
__device__ __align__(16) uint4 g_bp[L * L * ZP * 4];
// y1: per site 4 u64 (t=0..3): {lo32=fp16 pair ch(2t,2t+1), hi32=fp16 pair ch(2t+8,2t+9)}
__device__ __align__(16) ull g_y1p[L * L * ZP * 4];
// B fragments: conv1 uint4 {bh0,bh1,bl0,bl1};
//              conv2 uint4 {nt0.b0, nt0.b1, nt1.b0, nt1.b1} (two n-tiles per frag)
__device__ __align__(16) uint4 g_Bf1[27 * 2 * 32];   // conv1, bf16 hi+lo
__device__ __align__(16) uint4 g_Bf2[27 * 2 * 32];   // conv2, fp16 single, nt-paired
__device__ float g_part[864 * 32];

// ---------------- helpers ----------------
__device__ __forceinline__ int wrapi(int a) {
    return a < 0 ? a + L : (a >= L ? a - L : a);
}
__device__ __forceinline__ float eluf(float x) {
    return x > 0.f ? x : (__expf(x) - 1.f);
}
__device__ __forceinline__ void split2bf(float v0, float v1, uint32_t& hi, uint32_t& lo) {
    __nv_bfloat16 h0 = __float2bfloat16(v0);
    __nv_bfloat16 h1 = __float2bfloat16(v1);
    __nv_bfloat16 l0 = __float2bfloat16(v0 - __bfloat162float(h0));
    __nv_bfloat16 l1 = __float2bfloat16(v1 - __bfloat162float(h1));
    hi = (uint32_t)__bfloat16_as_ushort(h0) | ((uint32_t)__bfloat16_as_ushort(h1) << 16);
    lo = (uint32_t)__bfloat16_as_ushort(l0) | ((uint32_t)__bfloat16_as_ushort(l1) << 16);
}
__device__ __forceinline__ uint32_t h2pack(float a, float b) {
    __half2 h = __floats2half2_rn(a, b);
    return *(uint32_t*)&h;
}

#define MMA_BF16(D, A0, A1, A2, A3, B0, B1)                                 \
    asm("mma.sync.aligned.m16n8k16.row.col.f32.bf16.bf16.f32 "              \
        "{%0,%1,%2,%3}, {%4,%5,%6,%7}, {%8,%9}, {%0,%1,%2,%3};"             \
        : "+f"((D)[0]), "+f"((D)[1]), "+f"((D)[2]), "+f"((D)[3])            \
        : "r"(A0), "r"(A1), "r"(A2), "r"(A3), "r"(B0), "r"(B1))

#define MMA_F16(D, A0, A1, A2, A3, B0, B1)                                  \
    asm("mma.sync.aligned.m16n8k16.row.col.f32.f16.f16.f32 "                \
        "{%0,%1,%2,%3}, {%4,%5,%6,%7}, {%8,%9}, {%0,%1,%2,%3};"             \
        : "+f"((D)[0]), "+f"((D)[1]), "+f"((D)[2]), "+f"((D)[3])            \
        : "r"(A0), "r"(A1), "r"(A2), "r"(A3), "r"(B0), "r"(B1))

// ---------------- Kernel 1: bonds (blocks <3456) + weight prep (blocks >=3456) ----------------
__global__ __launch_bounds__(256) void bonds_prep_kernel(const int* __restrict__ lx,
                                                         const float* __restrict__ tet,
                                                         const float* __restrict__ w1,
                                                         const float* __restrict__ w2) {
    if (blockIdx.x >= 3456) {
        // -------- weight prep part --------
        int i = (blockIdx.x - 3456) * 256 + threadIdx.x;
        if (i < 27 * 2 * 32) {  // conv1: bf16 hi+lo
            int lane = i & 31, nt = (i >> 5) & 1, tap = i >> 6;
            int t = lane & 3;
            int n = nt * 8 + (lane >> 2);
            int k0 = t * 2;
            float v00 = (k0 < 12)      ? w1[(tap * 12 + k0) * 16 + n]      : 0.f;
            float v01 = (k0 + 1 < 12)  ? w1[(tap * 12 + k0 + 1) * 16 + n]  : 0.f;
            float v10 = (k0 + 8 < 12)  ? w1[(tap * 12 + k0 + 8) * 16 + n]  : 0.f;
            float v11 = (k0 + 9 < 12)  ? w1[(tap * 12 + k0 + 9) * 16 + n]  : 0.f;
            uint4 o;
            split2bf(v00, v01, o.x, o.z);
            split2bf(v10, v11, o.y, o.w);
            g_Bf1[i] = o;
        }
        int j = i - 27 * 2 * 32;
        if (j >= 0 && j < 27 * 2 * 32) {  // conv2: fp16 single, two n-tiles per uint4
            int lane = j & 31, ntp = (j >> 5) & 1, tap = j >> 6;
            int t = lane & 3;
            int k0 = t * 2;
            int n0 = (ntp * 2) * 8 + (lane >> 2);
            int n1 = n0 + 8;
            uint4 o;
            o.x = h2pack(w2[(tap * 16 + k0) * 32 + n0],
                         w2[(tap * 16 + k0 + 1) * 32 + n0]);
            o.y = h2pack(w2[(tap * 16 + k0 + 8) * 32 + n0],
                         w2[(tap * 16 + k0 + 9) * 32 + n0]);
            o.z = h2pack(w2[(tap * 16 + k0) * 32 + n1],
                         w2[(tap * 16 + k0 + 1) * 32 + n1]);
            o.w = h2pack(w2[(tap * 16 + k0 + 8) * 32 + n1],
                         w2[(tap * 16 + k0 + 9) * 32 + n1]);
            g_Bf2[j] = o;
        }
        return;
    }

    // -------- bonds part --------
    int idx = blockIdx.x * 256 + threadIdx.x;
    if (idx >= L3) return;
    int z = idx % L;
    int y = (idx / L) % L;
    int x = idx / LL2;

    float t00 = tet[0], t01 = tet[1], t10 = tet[2], t11 = tet[3];
    float d00 = t00 * t00 + t01 * t01;
    float d01 = t00 * t10 + t01 * t11;
    float d11 = t10 * t10 + t11 * t11;
    float dt[4] = {d00, d01, d01, d11};

    int4 a = *(const int4*)&lx[idx * 4];
    int a0 = a.x, a1 = a.y, a2 = a.z, a3 = a.w;
    int xm = x ? x - 1 : L - 1;
    int ym = y ? y - 1 : L - 1;
    int zm = z ? z - 1 : L - 1;
    int b1 = lx[((xm * L + y) * L + z) * 4 + 1];
    int b2 = lx[((x * L + ym) * L + z) * 4 + 2];
    int b3 = lx[((x * L + y) * L + zm) * 4 + 3];

    float v[16];
    v[0] = dt[a0 * 2 + a1];  v[1] = dt[a0 * 2 + a2];  v[2]  = dt[a0 * 2 + a3];
    v[3] = dt[a0 * 2 + b1];  v[4] = dt[a0 * 2 + b2];  v[5]  = dt[a0 * 2 + b3];
    v[6] = dt[a1 * 2 + a2];  v[7] = dt[a2 * 2 + a3];  v[8]  = dt[a3 * 2 + a1];
    v[9] = dt[b1 * 2 + b2];  v[10] = dt[b2 * 2 + b3]; v[11] = dt[b3 * 2 + b1];
    v[12] = v[13] = v[14] = v[15] = 0.f;

    uint4 q[4];
#pragma unroll
    for (int t = 0; t < 4; t++) {
        split2bf(v[2 * t], v[2 * t + 1], q[t].x, q[t].y);
        split2bf(v[2 * t + 8], v[2 * t + 9], q[t].z, q[t].w);
    }

    size_t rb = (size_t)(x * L + y) * (ZP * 4);
    uint4* dst = &g_bp[rb + (size_t)(z + 1) * 4];
#pragma unroll
    for (int t = 0; t < 4; t++) dst[t] = q[t];
    if (z == 0) {
        uint4* d2 = &g_bp[rb + 97 * 4];
#pragma unroll
        for (int t = 0; t < 4; t++) d2[t] = q[t];
    }
    if (z == L - 1) {
        uint4* d2 = &g_bp[rb];
#pragma unroll
        for (int t = 0; t < 4; t++) d2[t] = q[t];
    }
}

// ---------------- conv1: bf16 3-term (R14 known-good), 1728 CTAs ----------------
// Warp tile = 32 z-consecutive sites. 8 warps/CTA, 2 tiles/warp.
__global__ __launch_bounds__(256, 2) void conv1_kernel(const float* __restrict__ bias) {
    extern __shared__ uint4 sB4[];
    const int tid = threadIdx.x;
    const int wid = tid >> 5, lane = tid & 31;
    const int t = lane & 3, r = lane >> 2;

    for (int i = tid; i < 27 * 2 * 32; i += 256) sB4[i] = __ldg(g_Bf1 + i);
    __syncthreads();

    const int wg = blockIdx.x * 8 + wid;

    for (int it = 0; it < 2; it++) {
        int tile = wg * 2 + it;
        int tz = tile % 3;
        int ty = (tile / 3) % L;
        int tx = tile / (3 * L);
        int z0 = tz * 32;
        const int laneoff = (z0 + r) * 4 + t;

        int xs[3], ys[3];
#pragma unroll
        for (int k = 0; k < 3; k++) { xs[k] = wrapi(tx + k - 1); ys[k] = wrapi(ty + k - 1); }

        float d[2][2][4];
#pragma unroll
        for (int nt = 0; nt < 2; nt++) {
            float b0 = __ldg(bias + nt * 8 + t * 2);
            float b1 = __ldg(bias + nt * 8 + t * 2 + 1);
            d[0][nt][0] = b0; d[0][nt][1] = b1; d[0][nt][2] = b0; d[0][nt][3] = b1;
            d[1][nt][0] = b0; d[1][nt][1] = b1; d[1][nt][2] = b0; d[1][nt][3] = b1;
        }

#pragma unroll
        for (int kd = 0; kd < 3; kd++) {
#pragma unroll
            for (int kh = 0; kh < 3; kh++) {
                const uint4* rp = g_bp + (size_t)((xs[kd] * L + ys[kh]) * (ZP * 4) + laneoff);
                uint4 q[3][4];
#pragma unroll
                for (int kw = 0; kw < 3; kw++)
#pragma unroll
                    for (int jj = 0; jj < 4; jj++)
                        q[kw][jj] = __ldg(rp + kw * 4 + jj * 32);
#pragma unroll
                for (int kw = 0; kw < 3; kw++) {
                    const int tap = (kd * 3 + kh) * 3 + kw;
#pragma unroll
                    for (int nt = 0; nt < 2; nt++) {
                        uint4 wb = sB4[(tap * 2 + nt) * 32 + lane];  // 1 LDS.128
#pragma unroll
                        for (int mt = 0; mt < 2; mt++) {
                            const uint4& za = q[kw][mt * 2];
                            const uint4& zb = q[kw][mt * 2 + 1];
                            MMA_BF16(d[mt][nt], za.x, zb.x, za.z, zb.z, wb.x, wb.y);
                            MMA_BF16(d[mt][nt], za.x, zb.x, za.z, zb.z, wb.z, wb.w);
                            MMA_BF16(d[mt][nt], za.y, zb.y, za.w, zb.w, wb.x, wb.y);
                        }
                    }
                }
            }
        }

        // ELU -> fp16 single-plane store (word t = {nt0 pair | nt1 pair}), z-halo dup
        size_t rb = (size_t)(tx * L + ty) * (ZP * 4);
#pragma unroll
        for (int mt = 0; mt < 2; mt++) {
            int za = z0 + mt * 16 + r;
            int zb = za + 8;
            ull va = (ull)h2pack(eluf(d[mt][0][0]), eluf(d[mt][0][1])) |
                     ((ull)h2pack(eluf(d[mt][1][0]), eluf(d[mt][1][1])) << 32);
            ull vb = (ull)h2pack(eluf(d[mt][0][2]), eluf(d[mt][0][3])) |
                     ((ull)h2pack(eluf(d[mt][1][2]), eluf(d[mt][1][3])) << 32);
            g_y1p[rb + (size_t)(za + 1) * 4 + t] = va;
            g_y1p[rb + (size_t)(zb + 1) * 4 + t] = vb;
            if (za == 0)     g_y1p[rb + 97 * 4 + t] = va;
            if (zb == L - 1) g_y1p[rb + t] = vb;
        }
    }
}

// ---------------- conv2: fp16 single-term, nt-paired B frags (R14 known-good) ----------------
__global__ __launch_bounds__(256, 3) void conv2_kernel(const float* __restrict__ bias) {
    extern __shared__ uint4 sB4c[];
    __shared__ float red[8][32];

    const int tid = threadIdx.x;
    const int wid = tid >> 5, lane = tid & 31;
    const int t = lane & 3, r = lane >> 2;

    for (int i = tid; i < 27 * 2 * 32; i += 256) sB4c[i] = __ldg(g_Bf2 + i);
    __syncthreads();

    const int wg = blockIdx.x * 8 + wid;

    float psum0[4], psum1[4];
#pragma unroll
    for (int nt = 0; nt < 4; nt++) { psum0[nt] = 0.f; psum1[nt] = 0.f; }

    // flattened tile coordinates: tile0 = wg*4; tz cycles 0,1,2, ty/tx carry
    int tz = (wg * 4) % 3;
    int rest = (wg * 4) / 3;
    int ty = rest % L;
    int tx = rest / L;

    for (int it = 0; it < 4; it++) {
        int z0 = tz * 32;
        const int laneoff = (z0 + r) * 4 + t;

        int xs[3], ys[3];
#pragma unroll
        for (int k = 0; k < 3; k++) { xs[k] = wrapi(tx + k - 1); ys[k] = wrapi(ty + k - 1); }

        float d[2][4][4];
#pragma unroll
        for (int nt = 0; nt < 4; nt++) {
            float b0 = __ldg(bias + nt * 8 + t * 2);
            float b1 = __ldg(bias + nt * 8 + t * 2 + 1);
            d[0][nt][0] = b0; d[0][nt][1] = b1; d[0][nt][2] = b0; d[0][nt][3] = b1;
            d[1][nt][0] = b0; d[1][nt][1] = b1; d[1][nt][2] = b0; d[1][nt][3] = b1;
        }

#pragma unroll
        for (int kd = 0; kd < 3; kd++) {
#pragma unroll
            for (int kh = 0; kh < 3; kh++) {
                const uint2* rp = (const uint2*)g_y1p +
                                  (size_t)((xs[kd] * L + ys[kh]) * (ZP * 4) + laneoff);
                uint2 q[3][4];
#pragma unroll
                for (int kw = 0; kw < 3; kw++)
#pragma unroll
                    for (int jj = 0; jj < 4; jj++)
                        q[kw][jj] = __ldg(rp + kw * 4 + jj * 32);
#pragma unroll
                for (int kw = 0; kw < 3; kw++) {
                    const int tap = (kd * 3 + kh) * 3 + kw;
#pragma unroll
                    for (int ntp = 0; ntp < 2; ntp++) {
                        uint4 wb = sB4c[(tap * 2 + ntp) * 32 + lane];  // 1 LDS.128 -> 2 nt
#pragma unroll
                        for (int mt = 0; mt < 2; mt++) {
                            const uint2& za = q[kw][mt * 2];
                            const uint2& zb = q[kw][mt * 2 + 1];
                            MMA_F16(d[mt][2 * ntp],     za.x, zb.x, za.y, zb.y, wb.x, wb.y);
                            MMA_F16(d[mt][2 * ntp + 1], za.x, zb.x, za.y, zb.y, wb.z, wb.w);
                        }
                    }
                }
            }
        }

#pragma unroll
        for (int nt = 0; nt < 4; nt++) {
            psum0[nt] += eluf(d[0][nt][0]) + eluf(d[0][nt][2]) +
                         eluf(d[1][nt][0]) + eluf(d[1][nt][2]);
            psum1[nt] += eluf(d[0][nt][1]) + eluf(d[0][nt][3]) +
                         eluf(d[1][nt][1]) + eluf(d[1][nt][3]);
        }

        // increment tile coordinates (tz cycles 0..2 with ty/tx carry)
        if (++tz == 3) { tz = 0; if (++ty == L) { ty = 0; tx++; } }
    }

    // deterministic reduction over row-slots r (lane bits 2..4)
#pragma unroll
    for (int off = 4; off <= 16; off <<= 1)
#pragma unroll
        for (int nt = 0; nt < 4; nt++) {
            psum0[nt] += __shfl_xor_sync(0xffffffffu, psum0[nt], off);
            psum1[nt] += __shfl_xor_sync(0xffffffffu, psum1[nt], off);
        }
    if (r == 0) {
#pragma unroll
        for (int nt = 0; nt < 4; nt++) {
            red[wid][nt * 8 + t * 2] = psum0[nt];
            red[wid][nt * 8 + t * 2 + 1] = psum1[nt];
        }
    }
    __syncthreads();
    if (tid < 32) {
        float s = 0.f;
#pragma unroll
        for (int w = 0; w < 8; w++) s += red[w][tid];
        g_part[blockIdx.x * 32 + tid] = s;
    }
}

// ---------------- final reduction (deterministic, 1024 threads) ----------------
__global__ __launch_bounds__(1024) void final_kernel(const float* __restrict__ wd,
                                                     float* __restrict__ out) {
    __shared__ float sm[1024];
    int tt = threadIdx.x, ch = tt & 31, grp = tt >> 5;  // 32 groups of 32 channels
    float s = 0.f;
    for (int b = grp; b < 864; b += 32) s += g_part[b * 32 + ch];  // 27 indep loads
    sm[tt] = s;
    __syncthreads();
    if (tt < 32) {
        float v = 0.f;
#pragma unroll
        for (int g = 0; g < 32; g++) v += sm[g * 32 + tt];
        v = (v / (float)L3) * __ldg(wd + tt);
#pragma unroll
        for (int off = 16; off; off >>= 1)
            v += __shfl_xor_sync(0xffffffffu, v, off);
        if (tt == 0) out[0] = v;
    }
}

// ---------------- launch ----------------
extern "C" void kernel_launch(void* const* d_in, const int* in_sizes, int n_in,
                              void* d_out, int out_size) {
    (void)in_sizes; (void)n_in; (void)out_size;
    const int*   lx  = (const int*)d_in[0];
    const float* tet = (const float*)d_in[1];
    const float* w1  = (const float*)d_in[2];
    const float* b1  = (const float*)d_in[3];
    const float* w2  = (const float*)d_in[4];
    const float* b2  = (const float*)d_in[5];
    const float* wd  = (const float*)d_in[6];

    const int SMEM1 = 27 * 2 * 32 * 16;  // 27648 B
    const int SMEM2 = 27 * 2 * 32 * 16;  // 27648 B
    cudaFuncSetAttribute(conv1_kernel,
                         cudaFuncAttributeMaxDynamicSharedMemorySize, SMEM1);
    cudaFuncSetAttribute(conv2_kernel,
                         cudaFuncAttributeMaxDynamicSharedMemorySize, SMEM2);

    bonds_prep_kernel<<<3456 + 14, 256>>>(lx, tet, w1, w2);  // bonds + fused weight prep
    conv1_kernel<<<1728, 256, SMEM1>>>(b1);
    conv2_kernel<<<864, 256, SMEM2>>>(b2);
    final_kernel<<<1, 1024>>>(wd, (float*)d_out);
}

// round 17
// speedup vs baseline: 1.1006x; 1.0280x over previous
#include <cuda_runtime.h>
#include <cuda_bf16.h>
#include <cuda_fp16.h>
#include <stdint.h>
#include <math.h>

#define L 96
#define LL2 (L*L)
#define L3 (L*L*L)
#define ZP 98                 // z halo: zp=0 <-> z=95, zp=1..96 <-> z=0..95, zp=97 <-> z=0

typedef unsigned long long ull;

// ---------------- device scratch (allocation-free rule) ----------------
// bonds: per site 4 uint4 (t=0..3): {x=bf16hi pair ch(2t,2t+1), y=bf16lo pair,
//                                    z=bf16hi pair ch(2t+8,2t+9), w=bf16lo pair}
__device__ __align__(16) uint4 g_bp[L * L * ZP * 4];
// y1: per site 4 u64 (t=0..3): {lo32=fp16 pair ch(2t,2t+1), hi32=fp16 pair ch(2t+8,2t+9)}
__device__ __align__(16) ull g_y1p[L * L * ZP * 4];
// B fragments: conv1 uint4 {bh0,bh1,bl0,bl1};
//              conv2 uint4 {nt0.b0, nt0.b1, nt1.b0, nt1.b1} (two n-tiles per frag)
__device__ __align__(16) uint4 g_Bf1[27 * 2 * 32];   // conv1, bf16 hi+lo
__device__ __align__(16) uint4 g_Bf2[27 * 2 * 32];   // conv2, fp16 single, nt-paired
__device__ float g_part[864 * 32];

// ---------------- helpers ----------------
__device__ __forceinline__ int wrapi(int a) {
    return a < 0 ? a + L : (a >= L ? a - L : a);
}
__device__ __forceinline__ float eluf(float x) {
    return x > 0.f ? x : (__expf(x) - 1.f);
}
__device__ __forceinline__ void split2bf(float v0, float v1, uint32_t& hi, uint32_t& lo) {
    __nv_bfloat16 h0 = __float2bfloat16(v0);
    __nv_bfloat16 h1 = __float2bfloat16(v1);
    __nv_bfloat16 l0 = __float2bfloat16(v0 - __bfloat162float(h0));
    __nv_bfloat16 l1 = __float2bfloat16(v1 - __bfloat162float(h1));
    hi = (uint32_t)__bfloat16_as_ushort(h0) | ((uint32_t)__bfloat16_as_ushort(h1) << 16);
    lo = (uint32_t)__bfloat16_as_ushort(l0) | ((uint32_t)__bfloat16_as_ushort(l1) << 16);
}
__device__ __forceinline__ uint32_t h2pack(float a, float b) {
    __half2 h = __floats2half2_rn(a, b);
    return *(uint32_t*)&h;
}

#define MMA_BF16(D, A0, A1, A2, A3, B0, B1)                                 \
    asm("mma.sync.aligned.m16n8k16.row.col.f32.bf16.bf16.f32 "              \
        "{%0,%1,%2,%3}, {%4,%5,%6,%7}, {%8,%9}, {%0,%1,%2,%3};"             \
        : "+f"((D)[0]), "+f"((D)[1]), "+f"((D)[2]), "+f"((D)[3])            \
        : "r"(A0), "r"(A1), "r"(A2), "r"(A3), "r"(B0), "r"(B1))

#define MMA_F16(D, A0, A1, A2, A3, B0, B1)                                  \
    asm("mma.sync.aligned.m16n8k16.row.col.f32.f16.f16.f32 "                \
        "{%0,%1,%2,%3}, {%4,%5,%6,%7}, {%8,%9}, {%0,%1,%2,%3};"             \
        : "+f"((D)[0]), "+f"((D)[1]), "+f"((D)[2]), "+f"((D)[3])            \
        : "r"(A0), "r"(A1), "r"(A2), "r"(A3), "r"(B0), "r"(B1))

// ---------------- Kernel 1: bonds (blocks <3456) + weight prep (blocks >=3456) ----------------
__global__ __launch_bounds__(256) void bonds_prep_kernel(const int* __restrict__ lx,
                                                         const float* __restrict__ tet,
                                                         const float* __restrict__ w1,
                                                         const float* __restrict__ w2) {
    if (blockIdx.x >= 3456) {
        // -------- weight prep part --------
        int i = (blockIdx.x - 3456) * 256 + threadIdx.x;
        if (i < 27 * 2 * 32) {  // conv1: bf16 hi+lo
            int lane = i & 31, nt = (i >> 5) & 1, tap = i >> 6;
            int t = lane & 3;
            int n = nt * 8 + (lane >> 2);
            int k0 = t * 2;
            float v00 = (k0 < 12)      ? w1[(tap * 12 + k0) * 16 + n]      : 0.f;
            float v01 = (k0 + 1 < 12)  ? w1[(tap * 12 + k0 + 1) * 16 + n]  : 0.f;
            float v10 = (k0 + 8 < 12)  ? w1[(tap * 12 + k0 + 8) * 16 + n]  : 0.f;
            float v11 = (k0 + 9 < 12)  ? w1[(tap * 12 + k0 + 9) * 16 + n]  : 0.f;
            uint4 o;
            split2bf(v00, v01, o.x, o.z);
            split2bf(v10, v11, o.y, o.w);
            g_Bf1[i] = o;
        }
        int j = i - 27 * 2 * 32;
        if (j >= 0 && j < 27 * 2 * 32) {  // conv2: fp16 single, two n-tiles per uint4
            int lane = j & 31, ntp = (j >> 5) & 1, tap = j >> 6;
            int t = lane & 3;
            int k0 = t * 2;
            int n0 = (ntp * 2) * 8 + (lane >> 2);
            int n1 = n0 + 8;
            uint4 o;
            o.x = h2pack(w2[(tap * 16 + k0) * 32 + n0],
                         w2[(tap * 16 + k0 + 1) * 32 + n0]);
            o.y = h2pack(w2[(tap * 16 + k0 + 8) * 32 + n0],
                         w2[(tap * 16 + k0 + 9) * 32 + n0]);
            o.z = h2pack(w2[(tap * 16 + k0) * 32 + n1],
                         w2[(tap * 16 + k0 + 1) * 32 + n1]);
            o.w = h2pack(w2[(tap * 16 + k0 + 8) * 32 + n1],
                         w2[(tap * 16 + k0 + 9) * 32 + n1]);
            g_Bf2[j] = o;
        }
        return;
    }

    // -------- bonds part --------
    int idx = blockIdx.x * 256 + threadIdx.x;
    if (idx >= L3) return;
    int z = idx % L;
    int y = (idx / L) % L;
    int x = idx / LL2;

    float t00 = tet[0], t01 = tet[1], t10 = tet[2], t11 = tet[3];
    float d00 = t00 * t00 + t01 * t01;
    float d01 = t00 * t10 + t01 * t11;
    float d11 = t10 * t10 + t11 * t11;
    float dt[4] = {d00, d01, d01, d11};

    int4 a = *(const int4*)&lx[idx * 4];
    int a0 = a.x, a1 = a.y, a2 = a.z, a3 = a.w;
    int xm = x ? x - 1 : L - 1;
    int ym = y ? y - 1 : L - 1;
    int zm = z ? z - 1 : L - 1;
    int b1 = lx[((xm * L + y) * L + z) * 4 + 1];
    int b2 = lx[((x * L + ym) * L + z) * 4 + 2];
    int b3 = lx[((x * L + y) * L + zm) * 4 + 3];

    float v[16];
    v[0] = dt[a0 * 2 + a1];  v[1] = dt[a0 * 2 + a2];  v[2]  = dt[a0 * 2 + a3];
    v[3] = dt[a0 * 2 + b1];  v[4] = dt[a0 * 2 + b2];  v[5]  = dt[a0 * 2 + b3];
    v[6] = dt[a1 * 2 + a2];  v[7] = dt[a2 * 2 + a3];  v[8]  = dt[a3 * 2 + a1];
    v[9] = dt[b1 * 2 + b2];  v[10] = dt[b2 * 2 + b3]; v[11] = dt[b3 * 2 + b1];
    v[12] = v[13] = v[14] = v[15] = 0.f;

    uint4 q[4];
#pragma unroll
    for (int t = 0; t < 4; t++) {
        split2bf(v[2 * t], v[2 * t + 1], q[t].x, q[t].y);
        split2bf(v[2 * t + 8], v[2 * t + 9], q[t].z, q[t].w);
    }

    size_t rb = (size_t)(x * L + y) * (ZP * 4);
    uint4* dst = &g_bp[rb + (size_t)(z + 1) * 4];
#pragma unroll
    for (int t = 0; t < 4; t++) dst[t] = q[t];
    if (z == 0) {
        uint4* d2 = &g_bp[rb + 97 * 4];
#pragma unroll
        for (int t = 0; t < 4; t++) d2[t] = q[t];
    }
    if (z == L - 1) {
        uint4* d2 = &g_bp[rb];
#pragma unroll
        for (int t = 0; t < 4; t++) d2[t] = q[t];
    }
}

// ---------------- conv1: bf16 3-term (R14 known-good), 1728 CTAs ----------------
// Warp tile = 32 z-consecutive sites. 8 warps/CTA, 2 tiles/warp.
__global__ __launch_bounds__(256, 2) void conv1_kernel(const float* __restrict__ bias) {
    extern __shared__ uint4 sB4[];
    const int tid = threadIdx.x;
    const int wid = tid >> 5, lane = tid & 31;
    const int t = lane & 3, r = lane >> 2;

    for (int i = tid; i < 27 * 2 * 32; i += 256) sB4[i] = __ldg(g_Bf1 + i);
    __syncthreads();

    const int wg = blockIdx.x * 8 + wid;

    for (int it = 0; it < 2; it++) {
        int tile = wg * 2 + it;
        int tz = tile % 3;
        int ty = (tile / 3) % L;
        int tx = tile / (3 * L);
        int z0 = tz * 32;
        const int laneoff = (z0 + r) * 4 + t;

        int xs[3], ys[3];
#pragma unroll
        for (int k = 0; k < 3; k++) { xs[k] = wrapi(tx + k - 1); ys[k] = wrapi(ty + k - 1); }

        float d[2][2][4];
#pragma unroll
        for (int nt = 0; nt < 2; nt++) {
            float b0 = __ldg(bias + nt * 8 + t * 2);
            float b1 = __ldg(bias + nt * 8 + t * 2 + 1);
            d[0][nt][0] = b0; d[0][nt][1] = b1; d[0][nt][2] = b0; d[0][nt][3] = b1;
            d[1][nt][0] = b0; d[1][nt][1] = b1; d[1][nt][2] = b0; d[1][nt][3] = b1;
        }

#pragma unroll
        for (int kd = 0; kd < 3; kd++) {
#pragma unroll
            for (int kh = 0; kh < 3; kh++) {
                const uint4* rp = g_bp + (size_t)((xs[kd] * L + ys[kh]) * (ZP * 4) + laneoff);
                uint4 q[3][4];
#pragma unroll
                for (int kw = 0; kw < 3; kw++)
#pragma unroll
                    for (int jj = 0; jj < 4; jj++)
                        q[kw][jj] = __ldg(rp + kw * 4 + jj * 32);
#pragma unroll
                for (int kw = 0; kw < 3; kw++) {
                    const int tap = (kd * 3 + kh) * 3 + kw;
#pragma unroll
                    for (int nt = 0; nt < 2; nt++) {
                        uint4 wb = sB4[(tap * 2 + nt) * 32 + lane];  // 1 LDS.128
#pragma unroll
                        for (int mt = 0; mt < 2; mt++) {
                            const uint4& za = q[kw][mt * 2];
                            const uint4& zb = q[kw][mt * 2 + 1];
                            MMA_BF16(d[mt][nt], za.x, zb.x, za.z, zb.z, wb.x, wb.y);
                            MMA_BF16(d[mt][nt], za.x, zb.x, za.z, zb.z, wb.z, wb.w);
                            MMA_BF16(d[mt][nt], za.y, zb.y, za.w, zb.w, wb.x, wb.y);
                        }
                    }
                }
            }
        }

        // ELU -> fp16 single-plane store (word t = {nt0 pair | nt1 pair}), z-halo dup
        size_t rb = (size_t)(tx * L + ty) * (ZP * 4);
#pragma unroll
        for (int mt = 0; mt < 2; mt++) {
            int za = z0 + mt * 16 + r;
            int zb = za + 8;
            ull va = (ull)h2pack(eluf(d[mt][0][0]), eluf(d[mt][0][1])) |
                     ((ull)h2pack(eluf(d[mt][1][0]), eluf(d[mt][1][1])) << 32);
            ull vb = (ull)h2pack(eluf(d[mt][0][2]), eluf(d[mt][0][3])) |
                     ((ull)h2pack(eluf(d[mt][1][2]), eluf(d[mt][1][3])) << 32);
            g_y1p[rb + (size_t)(za + 1) * 4 + t] = va;
            g_y1p[rb + (size_t)(zb + 1) * 4 + t] = vb;
            if (za == 0)     g_y1p[rb + 97 * 4 + t] = va;
            if (zb == L - 1) g_y1p[rb + t] = vb;
        }
    }
}

// ---------------- conv2: fp16 single-term, nt-paired B frags (R14 known-good) ----------------
__global__ __launch_bounds__(256, 3) void conv2_kernel(const float* __restrict__ bias) {
    extern __shared__ uint4 sB4c[];
    __shared__ float red[8][32];

    const int tid = threadIdx.x;
    const int wid = tid >> 5, lane = tid & 31;
    const int t = lane & 3, r = lane >> 2;

    for (int i = tid; i < 27 * 2 * 32; i += 256) sB4c[i] = __ldg(g_Bf2 + i);
    __syncthreads();

    const int wg = blockIdx.x * 8 + wid;

    float psum0[4], psum1[4];
#pragma unroll
    for (int nt = 0; nt < 4; nt++) { psum0[nt] = 0.f; psum1[nt] = 0.f; }

    for (int it = 0; it < 4; it++) {
        int tile = wg * 4 + it;
        int tz = tile % 3;
        int ty = (tile / 3) % L;
        int tx = tile / (3 * L);
        int z0 = tz * 32;
        const int laneoff = (z0 + r) * 4 + t;

        int xs[3], ys[3];
#pragma unroll
        for (int k = 0; k < 3; k++) { xs[k] = wrapi(tx + k - 1); ys[k] = wrapi(ty + k - 1); }

        float d[2][4][4];
#pragma unroll
        for (int nt = 0; nt < 4; nt++) {
            float b0 = __ldg(bias + nt * 8 + t * 2);
            float b1 = __ldg(bias + nt * 8 + t * 2 + 1);
            d[0][nt][0] = b0; d[0][nt][1] = b1; d[0][nt][2] = b0; d[0][nt][3] = b1;
            d[1][nt][0] = b0; d[1][nt][1] = b1; d[1][nt][2] = b0; d[1][nt][3] = b1;
        }

#pragma unroll
        for (int kd = 0; kd < 3; kd++) {
#pragma unroll
            for (int kh = 0; kh < 3; kh++) {
                const uint2* rp = (const uint2*)g_y1p +
                                  (size_t)((xs[kd] * L + ys[kh]) * (ZP * 4) + laneoff);
                uint2 q[3][4];
#pragma unroll
                for (int kw = 0; kw < 3; kw++)
#pragma unroll
                    for (int jj = 0; jj < 4; jj++)
                        q[kw][jj] = __ldg(rp + kw * 4 + jj * 32);
#pragma unroll
                for (int kw = 0; kw < 3; kw++) {
                    const int tap = (kd * 3 + kh) * 3 + kw;
#pragma unroll
                    for (int ntp = 0; ntp < 2; ntp++) {
                        uint4 wb = sB4c[(tap * 2 + ntp) * 32 + lane];  // 1 LDS.128 -> 2 nt
#pragma unroll
                        for (int mt = 0; mt < 2; mt++) {
                            const uint2& za = q[kw][mt * 2];
                            const uint2& zb = q[kw][mt * 2 + 1];
                            MMA_F16(d[mt][2 * ntp],     za.x, zb.x, za.y, zb.y, wb.x, wb.y);
                            MMA_F16(d[mt][2 * ntp + 1], za.x, zb.x, za.y, zb.y, wb.z, wb.w);
                        }
                    }
                }
            }
        }

#pragma unroll
        for (int nt = 0; nt < 4; nt++) {
            psum0[nt] += eluf(d[0][nt][0]) + eluf(d[0][nt][2]) +
                         eluf(d[1][nt][0]) + eluf(d[1][nt][2]);
            psum1[nt] += eluf(d[0][nt][1]) + eluf(d[0][nt][3]) +
                         eluf(d[1][nt][1]) + eluf(d[1][nt][3]);
        }
    }

    // deterministic reduction over row-slots r (lane bits 2..4)
#pragma unroll
    for (int off = 4; off <= 16; off <<= 1)
#pragma unroll
        for (int nt = 0; nt < 4; nt++) {
            psum0[nt] += __shfl_xor_sync(0xffffffffu, psum0[nt], off);
            psum1[nt] += __shfl_xor_sync(0xffffffffu, psum1[nt], off);
        }
    if (r == 0) {
#pragma unroll
        for (int nt = 0; nt < 4; nt++) {
            red[wid][nt * 8 + t * 2] = psum0[nt];
            red[wid][nt * 8 + t * 2 + 1] = psum1[nt];
        }
    }
    __syncthreads();
    if (tid < 32) {
        float s = 0.f;
#pragma unroll
        for (int w = 0; w < 8; w++) s += red[w][tid];
        g_part[blockIdx.x * 32 + tid] = s;
    }
}

// ---------------- final reduction (deterministic, 1024 threads) ----------------
__global__ __launch_bounds__(1024) void final_kernel(const float* __restrict__ wd,
                                                     float* __restrict__ out) {
    __shared__ float sm[1024];
    int tt = threadIdx.x, ch = tt & 31, grp = tt >> 5;  // 32 groups of 32 channels
    float s = 0.f;
    for (int b = grp; b < 864; b += 32) s += g_part[b * 32 + ch];  // 27 indep loads
    sm[tt] = s;
    __syncthreads();
    if (tt < 32) {
        float v = 0.f;
#pragma unroll
        for (int g = 0; g < 32; g++) v += sm[g * 32 + tt];
        v = (v / (float)L3) * __ldg(wd + tt);
#pragma unroll
        for (int off = 16; off; off >>= 1)
            v += __shfl_xor_sync(0xffffffffu, v, off);
        if (tt == 0) out[0] = v;
    }
}

// ---------------- launch ----------------
extern "C" void kernel_launch(void* const* d_in, const int* in_sizes, int n_in,
                              void* d_out, int out_size) {
    (void)in_sizes; (void)n_in; (void)out_size;
    const int*   lx  = (const int*)d_in[0];
    const float* tet = (const float*)d_in[1];
    const float* w1  = (const float*)d_in[2];
    const float* b1  = (const float*)d_in[3];
    const float* w2  = (const float*)d_in[4];
    const float* b2  = (const float*)d_in[5];
    const float* wd  = (const float*)d_in[6];

    const int SMEM1 = 27 * 2 * 32 * 16;  // 27648 B
    const int SMEM2 = 27 * 2 * 32 * 16;  // 27648 B
    cudaFuncSetAttribute(conv1_kernel,
                         cudaFuncAttributeMaxDynamicSharedMemorySize, SMEM1);
    cudaFuncSetAttribute(conv2_kernel,
                         cudaFuncAttributeMaxDynamicSharedMemorySize, SMEM2);

    bonds_prep_kernel<<<3456 + 14, 256>>>(lx, tet, w1, w2);  // bonds + fused weight prep
    conv1_kernel<<<1728, 256, SMEM1>>>(b1);
    conv2_kernel<<<864, 256, SMEM2>>>(b2);
    final_kernel<<<1, 1024>>>(wd, (float*)d_out);
}